// round 1
// baseline (speedup 1.0000x reference)
#include <cuda_runtime.h>
#include <math.h>

#define B_SZ 4
#define N_PTS 8192
#define KNN 20
#define NCH 16
#define TILE 2048
#define THREADS 256

// Scratch (no allocations allowed): per-point 20th distance + global sum/sumsq.
__device__ float g_dmax[B_SZ * N_PTS];
__device__ float g_stats[2];

__global__ void init_kernel() {
    g_stats[0] = 0.f;
    g_stats[1] = 0.f;
}

__global__ __launch_bounds__(THREADS) void knn_kernel(const float* __restrict__ x) {
    __shared__ float4 sh[TILE];
    __shared__ float red1[THREADS / 32], red2[THREADS / 32];

    const int blocks_per_batch = N_PTS / THREADS;            // 32
    const int b = blockIdx.x / blocks_per_batch;
    const int n = (blockIdx.x % blocks_per_batch) * THREADS + threadIdx.x;

    const float* xb = x + (size_t)b * 3 * N_PTS;
    const float qx = xb[n];
    const float qy = xb[N_PTS + n];
    const float qz = xb[2 * N_PTS + n];
    const float qsq = fmaf(qx, qx, fmaf(qy, qy, qz * qz));

    const float INF = __int_as_float(0x7f800000);
    float r[KNN];
#pragma unroll
    for (int k = 0; k < KNN; k++) r[k] = INF;

    for (int t = 0; t < N_PTS; t += TILE) {
        __syncthreads();
        for (int i = threadIdx.x; i < TILE; i += THREADS) {
            float px = xb[t + i];
            float py = xb[N_PTS + t + i];
            float pz = xb[2 * N_PTS + t + i];
            sh[i] = make_float4(px, py, pz, fmaf(px, px, fmaf(py, py, pz * pz)));
        }
        __syncthreads();

#pragma unroll 4
        for (int i = 0; i < TILE; i++) {
            float4 p = sh[i];  // uniform address -> LDS.128 broadcast
            float dot = fmaf(qx, p.x, fmaf(qy, p.y, qz * p.z));
            float d2 = fmaf(-2.f, dot, qsq + p.w);
            d2 = fmaxf(d2, 0.f);
            if (__any_sync(0xffffffffu, d2 < r[KNN - 1])) {
                // lanes that don't insert push INF (no-op through the chain)
                float v = (d2 < r[KNN - 1]) ? d2 : INF;
#pragma unroll
                for (int k = 0; k < KNN; k++) {
                    float o = r[k];
                    bool c = v < o;
                    r[k] = c ? v : o;
                    v = c ? o : v;
                }
            }
        }
    }

    // finalize: distances of the 20 smallest d2
    float s1 = 0.f, s2 = 0.f, dmax = 0.f;
#pragma unroll
    for (int k = 0; k < KNN; k++) {
        float d2 = r[k];
        float d = (d2 > 0.f) ? sqrtf(d2) : 0.f;
        s1 += d;
        s2 += d2;          // dist^2 == clamped d2 in all cases
        if (k == KNN - 1) dmax = d;
    }
    g_dmax[b * N_PTS + n] = dmax;

    // block reduce of s1/s2 -> 2 atomics per block
#pragma unroll
    for (int o = 16; o > 0; o >>= 1) {
        s1 += __shfl_xor_sync(0xffffffffu, s1, o);
        s2 += __shfl_xor_sync(0xffffffffu, s2, o);
    }
    int w = threadIdx.x >> 5;
    if ((threadIdx.x & 31) == 0) { red1[w] = s1; red2[w] = s2; }
    __syncthreads();
    if (threadIdx.x == 0) {
        float a = 0.f, c = 0.f;
#pragma unroll
        for (int i = 0; i < THREADS / 32; i++) { a += red1[i]; c += red2[i]; }
        atomicAdd(&g_stats[0], a);
        atomicAdd(&g_stats[1], c);
    }
}

__global__ __launch_bounds__(256) void out_kernel(const float* __restrict__ conv_w,
                                                  const float* __restrict__ gamma,
                                                  const float* __restrict__ beta,
                                                  float* __restrict__ out) {
    __shared__ float s_s[NCH], s_t[NCH];
    const float Mcnt = (float)(B_SZ * N_PTS * KNN);
    if (threadIdx.x < NCH) {
        int c = threadIdx.x;
        float m = g_stats[0] / Mcnt;
        float v = g_stats[1] / Mcnt - m * m;
        v = fmaxf(v, 0.f);
        float w = conv_w[c];
        float s = gamma[c] * w * rsqrtf(fmaf(w * w, v, 1e-5f));
        s_s[c] = s;
        s_t[c] = beta[c] - s * m;   // y = s*knn + (beta - s*m); conv_b cancels in BN
    }
    __syncthreads();

    int q = blockIdx.x * blockDim.x + threadIdx.x;   // 0 .. B*N-1
    int b = q / N_PTS, n = q % N_PTS;
    float dmax = g_dmax[q];
#pragma unroll
    for (int c = 0; c < NCH; c++) {
        float s = s_s[c];
        float knn = (s >= 0.f) ? dmax : 0.f;  // min knn is always 0 (self-distance)
        float y = fmaf(s, knn, s_t[c]);
        y = (y >= 0.f) ? y : 0.2f * y;        // LeakyReLU, monotone -> commutes with max_k
        out[((size_t)b * NCH + c) * N_PTS + n] = y;
    }
}

extern "C" void kernel_launch(void* const* d_in, const int* in_sizes, int n_in,
                              void* d_out, int out_size) {
    const float* x      = (const float*)d_in[0];
    const float* conv_w = (const float*)d_in[1];
    // d_in[2] = conv_b: cancels analytically, unused
    const float* gamma  = (const float*)d_in[3];
    const float* beta   = (const float*)d_in[4];
    float* out = (float*)d_out;

    init_kernel<<<1, 1>>>();
    knn_kernel<<<(B_SZ * N_PTS) / THREADS, THREADS>>>(x);
    out_kernel<<<(B_SZ * N_PTS) / 256, 256>>>(conv_w, gamma, beta, out);
}

// round 2
// speedup vs baseline: 1.3654x; 1.3654x over previous
#include <cuda_runtime.h>
#include <math.h>

#define B_SZ 4
#define N_PTS 8192
#define KNN 20
#define NCH 16
#define TILE 2048
#define THREADS 256
#define NBLK ((B_SZ * N_PTS) / THREADS)   // 128 knn blocks

// Scratch (allocations forbidden): per-point 20th distance, per-block partial
// sums (double, fixes BN-variance cancellation), and the reduced mean/var.
__device__ float  g_dmax[B_SZ * N_PTS];
__device__ double g_p1[NBLK];
__device__ double g_p2[NBLK];
__device__ float  g_mv[2];

__global__ __launch_bounds__(THREADS) void knn_kernel(const float* __restrict__ x) {
    __shared__ float4 sh[TILE];
    __shared__ double red1[THREADS / 32], red2[THREADS / 32];

    const int blocks_per_batch = N_PTS / THREADS;            // 32
    const int b = blockIdx.x / blocks_per_batch;
    const int n = (blockIdx.x % blocks_per_batch) * THREADS + threadIdx.x;

    const float* xb = x + (size_t)b * 3 * N_PTS;
    const float qx = xb[n];
    const float qy = xb[N_PTS + n];
    const float qz = xb[2 * N_PTS + n];
    const float qsq = fmaf(qx, qx, fmaf(qy, qy, qz * qz));

    const float INF = __int_as_float(0x7f800000);
    float r[KNN];
#pragma unroll
    for (int k = 0; k < KNN; k++) r[k] = INF;

    for (int t = 0; t < N_PTS; t += TILE) {
        __syncthreads();
        for (int i = threadIdx.x; i < TILE; i += THREADS) {
            float px = xb[t + i];
            float py = xb[N_PTS + t + i];
            float pz = xb[2 * N_PTS + t + i];
            sh[i] = make_float4(px, py, pz, fmaf(px, px, fmaf(py, py, pz * pz)));
        }
        __syncthreads();

#pragma unroll 8
        for (int i = 0; i < TILE; i++) {
            float4 p = sh[i];  // uniform address -> LDS.128 broadcast
            float dot = fmaf(qx, p.x, fmaf(qy, p.y, qz * p.z));
            float d2 = fmaf(-2.f, dot, qsq + p.w);   // self-pair -> exactly 0
            if (__any_sync(0xffffffffu, d2 < r[KNN - 1])) {
                // parallel sorted-insert: a[k] = min(a[k], max(a[k-1], v));
                // in-place descending uses old a[k-1]. v >= a[19] is a no-op,
                // so non-qualifying lanes need no select.
#pragma unroll
                for (int k = KNN - 1; k >= 1; k--)
                    r[k] = fminf(r[k], fmaxf(r[k - 1], d2));
                r[0] = fminf(r[0], d2);
            }
        }
    }

    // finalize: clamp, sqrt, accumulate stats in double
    double s1 = 0.0, s2 = 0.0;
#pragma unroll
    for (int k = 0; k < KNN; k++) {
        float d2 = fmaxf(r[k], 0.f);
        float d = sqrtf(d2);
        s1 += (double)d;
        s2 += (double)d2;
    }
    g_dmax[b * N_PTS + n] = sqrtf(fmaxf(r[KNN - 1], 0.f));

#pragma unroll
    for (int o = 16; o > 0; o >>= 1) {
        s1 += __shfl_xor_sync(0xffffffffu, s1, o);
        s2 += __shfl_xor_sync(0xffffffffu, s2, o);
    }
    int w = threadIdx.x >> 5;
    if ((threadIdx.x & 31) == 0) { red1[w] = s1; red2[w] = s2; }
    __syncthreads();
    if (threadIdx.x == 0) {
        double a = 0.0, c = 0.0;
#pragma unroll
        for (int i = 0; i < THREADS / 32; i++) { a += red1[i]; c += red2[i]; }
        g_p1[blockIdx.x] = a;
        g_p2[blockIdx.x] = c;
    }
}

__global__ void stats_kernel() {
    // one block, 128 threads: reduce per-block partials -> mean, biased var
    __shared__ double sr1[4], sr2[4];
    int t = threadIdx.x;
    double v1 = g_p1[t], v2 = g_p2[t];
#pragma unroll
    for (int o = 16; o > 0; o >>= 1) {
        v1 += __shfl_xor_sync(0xffffffffu, v1, o);
        v2 += __shfl_xor_sync(0xffffffffu, v2, o);
    }
    if ((t & 31) == 0) { sr1[t >> 5] = v1; sr2[t >> 5] = v2; }
    __syncthreads();
    if (t == 0) {
        double s1 = sr1[0] + sr1[1] + sr1[2] + sr1[3];
        double s2 = sr2[0] + sr2[1] + sr2[2] + sr2[3];
        const double M = (double)(B_SZ * N_PTS * KNN);
        double m = s1 / M;
        double var = s2 / M - m * m;
        if (var < 0.0) var = 0.0;
        g_mv[0] = (float)m;
        g_mv[1] = (float)var;
    }
}

__global__ __launch_bounds__(256) void out_kernel(const float* __restrict__ conv_w,
                                                  const float* __restrict__ gamma,
                                                  const float* __restrict__ beta,
                                                  float* __restrict__ out) {
    __shared__ float s_s[NCH], s_t[NCH];
    if (threadIdx.x < NCH) {
        int c = threadIdx.x;
        float m = g_mv[0];
        float v = g_mv[1];
        float w = conv_w[c];
        float s = gamma[c] * w * rsqrtf(fmaf(w * w, v, 1e-5f));
        s_s[c] = s;
        s_t[c] = beta[c] - s * m;   // y = s*knn + (beta - s*m); conv_b cancels in BN
    }
    __syncthreads();

    int q = blockIdx.x * blockDim.x + threadIdx.x;   // 0 .. B*N-1
    int b = q / N_PTS, n = q % N_PTS;
    float dmax = g_dmax[q];
#pragma unroll
    for (int c = 0; c < NCH; c++) {
        float s = s_s[c];
        float knn = (s >= 0.f) ? dmax : 0.f;  // min knn is always 0 (self-distance)
        float y = fmaf(s, knn, s_t[c]);
        y = (y >= 0.f) ? y : 0.2f * y;        // LeakyReLU, monotone -> commutes with max_k
        out[((size_t)b * NCH + c) * N_PTS + n] = y;
    }
}

extern "C" void kernel_launch(void* const* d_in, const int* in_sizes, int n_in,
                              void* d_out, int out_size) {
    const float* x      = (const float*)d_in[0];
    const float* conv_w = (const float*)d_in[1];
    // d_in[2] = conv_b: cancels analytically in training-mode BN, unused
    const float* gamma  = (const float*)d_in[3];
    const float* beta   = (const float*)d_in[4];
    float* out = (float*)d_out;

    knn_kernel<<<NBLK, THREADS>>>(x);
    stats_kernel<<<1, 128>>>();
    out_kernel<<<(B_SZ * N_PTS) / 256, 256>>>(conv_w, gamma, beta, out);
}